// round 1
// baseline (speedup 1.0000x reference)
#include <cuda_runtime.h>
#include <math.h>

// Problem constants
#define BB 8
#define NN 2048
#define UU 256
#define MROWS (BB*NN)     // 16384
#define MAXNBR 128        // density 0.008 -> ~16.4 nbrs/row; 128 is >20 sigma safe

// ---------------- device scratch (allocation-free rule: __device__ globals) ----
__device__ float g_h [MROWS*UU];
__device__ float g_q [MROWS*UU];
__device__ float g_k [MROWS*UU];
__device__ float g_v [MROWS*UU];
__device__ float g_t [MROWS*UU];
__device__ float g_y [MROWS*UU];
__device__ float g_kv[BB*UU*UU];
__device__ int   g_cols[MROWS*MAXNBR];
__device__ int   g_cnt [MROWS];

// ---------------- CSR build: one warp per row, deterministic ballot compaction
__global__ void csr_build(const float* __restrict__ adj) {
    int r    = blockIdx.x * 8 + (threadIdx.x >> 5);
    int lane = threadIdx.x & 31;
    const float* row = adj + (size_t)r * NN;
    int base = 0;
    for (int c0 = 0; c0 < NN; c0 += 32) {
        float a = row[c0 + lane];
        unsigned m = __ballot_sync(0xffffffffu, a != 0.0f);
        if (a != 0.0f) {
            int pos = base + __popc(m & ((1u << lane) - 1u));
            if (pos < MAXNBR) g_cols[r * MAXNBR + pos] = c0 + lane;
        }
        base += __popc(m);
    }
    if (lane == 0) g_cnt[r] = base < MAXNBR ? base : MAXNBR;
}

// ---------------- sparse adj @ x : one block (256 thr) per output row --------
__global__ void __launch_bounds__(256) spmm(const float* __restrict__ x,
                                            float* __restrict__ out) {
    __shared__ int cols[MAXNBR];
    int r   = blockIdx.x;
    int tid = threadIdx.x;
    int cnt = g_cnt[r];
    for (int i = tid; i < cnt; i += 256) cols[i] = g_cols[r * MAXNBR + i];
    __syncthreads();
    const float* xb = x + (size_t)(r >> 11) * NN * UU;  // batch base
    float a0 = 0.f, a1 = 0.f, a2 = 0.f, a3 = 0.f;
    int j = 0;
    for (; j + 4 <= cnt; j += 4) {
        a0 += xb[cols[j + 0] * UU + tid];
        a1 += xb[cols[j + 1] * UU + tid];
        a2 += xb[cols[j + 2] * UU + tid];
        a3 += xb[cols[j + 3] * UU + tid];
    }
    for (; j < cnt; j++) a0 += xb[cols[j] * UU + tid];
    out[(size_t)r * UU + tid] = (a0 + a1) + (a2 + a3);
}

// ---------------- generic fp32 GEMM  C[M,256] = epi(A[M,256] @ W[256,256]) ---
struct Epi {
    const float* bias;    // per-col bias (or null)
    const float* addsrc;  // same-shape residual add (or null)
    const float* mask;    // per-row mask (or null)
    const float* gamma;   // batchnorm (gamma!=null enables); beta/mean/var too
    const float* beta;
    const float* mean;
    const float* var;
    int act;              // 1 = silu
    int maskmode;         // 0 none, 1 before act, 2 after act
};

__global__ void __launch_bounds__(256, 2) gemm_k(const float* __restrict__ A,
                                                 const float* __restrict__ W,
                                                 float* __restrict__ C,
                                                 int perBatchW, Epi e) {
    __shared__ float As[16][128];
    __shared__ float Bs[16][64];
    int tid  = threadIdx.x;
    int row0 = blockIdx.x * 128;
    int col0 = blockIdx.y * 64;
    const float* Wb = W + (perBatchW ? (size_t)(row0 >> 11) * UU * UU : 0);
    int tr = tid >> 4, tc = tid & 15;
    float acc[8][4];
#pragma unroll
    for (int i = 0; i < 8; i++)
#pragma unroll
        for (int j = 0; j < 4; j++) acc[i][j] = 0.f;

    for (int k0 = 0; k0 < UU; k0 += 16) {
#pragma unroll
        for (int l = tid; l < 512; l += 256) {
            int ar = l >> 2, ac = (l & 3) * 4;
            float4 vv = *(const float4*)(A + (size_t)(row0 + ar) * UU + k0 + ac);
            As[ac + 0][ar] = vv.x;
            As[ac + 1][ar] = vv.y;
            As[ac + 2][ar] = vv.z;
            As[ac + 3][ar] = vv.w;
        }
        {
            int wr = tid >> 4, wc = (tid & 15) * 4;
            *(float4*)&Bs[wr][wc] =
                *(const float4*)(Wb + (size_t)(k0 + wr) * UU + col0 + wc);
        }
        __syncthreads();
#pragma unroll
        for (int kk = 0; kk < 16; kk++) {
            float4 a0 = *(float4*)&As[kk][tr * 8];
            float4 a1 = *(float4*)&As[kk][tr * 8 + 4];
            float4 bv = *(float4*)&Bs[kk][tc * 4];
            float am[8] = {a0.x, a0.y, a0.z, a0.w, a1.x, a1.y, a1.z, a1.w};
            float bm[4] = {bv.x, bv.y, bv.z, bv.w};
#pragma unroll
            for (int i = 0; i < 8; i++)
#pragma unroll
                for (int j = 0; j < 4; j++) acc[i][j] += am[i] * bm[j];
        }
        __syncthreads();
    }

#pragma unroll
    for (int i = 0; i < 8; i++) {
        int r = row0 + tr * 8 + i;
        float mk = e.maskmode ? e.mask[r] : 1.f;
#pragma unroll
        for (int j = 0; j < 4; j++) {
            int c = col0 + tc * 4 + j;
            float v = acc[i][j];
            if (e.bias)   v += e.bias[c];
            if (e.addsrc) v += e.addsrc[(size_t)r * UU + c];
            if (e.gamma)
                v = e.gamma[c] * (v - e.mean[c]) * rsqrtf(e.var[c] + 1e-3f) + e.beta[c];
            if (e.maskmode == 1) v *= mk;
            if (e.act) v = v * (1.f / (1.f + __expf(-v)));
            if (e.maskmode == 2) v *= mk;
            C[(size_t)r * UU + c] = v;
        }
    }
}

// ---------------- kv[b,d,e] = sum_n pk[b,n,d] * pv[b,n,e] --------------------
__global__ void __launch_bounds__(256) kv_k(const float* __restrict__ pk,
                                            const float* __restrict__ pv,
                                            float* __restrict__ kvout) {
    __shared__ float Ks[16][64];
    __shared__ float Vs[16][64];
    int tid = threadIdx.x;
    int d0 = blockIdx.x * 64, e0 = blockIdx.y * 64, b = blockIdx.z;
    const float* pkb = pk + (size_t)b * NN * UU;
    const float* pvb = pv + (size_t)b * NN * UU;
    int tr = tid >> 4, tc = tid & 15;
    int lr = tid >> 4, lc = (tid & 15) * 4;
    float acc[4][4];
#pragma unroll
    for (int i = 0; i < 4; i++)
#pragma unroll
        for (int j = 0; j < 4; j++) acc[i][j] = 0.f;

    for (int n0 = 0; n0 < NN; n0 += 16) {
        *(float4*)&Ks[lr][lc] = *(const float4*)(pkb + (size_t)(n0 + lr) * UU + d0 + lc);
        *(float4*)&Vs[lr][lc] = *(const float4*)(pvb + (size_t)(n0 + lr) * UU + e0 + lc);
        __syncthreads();
#pragma unroll
        for (int kk = 0; kk < 16; kk++) {
            float4 av = *(float4*)&Ks[kk][tr * 4];
            float4 bv = *(float4*)&Vs[kk][tc * 4];
            float am[4] = {av.x, av.y, av.z, av.w};
            float bm[4] = {bv.x, bv.y, bv.z, bv.w};
#pragma unroll
            for (int i = 0; i < 4; i++)
#pragma unroll
                for (int j = 0; j < 4; j++) acc[i][j] += am[i] * bm[j];
        }
        __syncthreads();
    }
#pragma unroll
    for (int i = 0; i < 4; i++)
#pragma unroll
        for (int j = 0; j < 4; j++)
            kvout[(size_t)b * UU * UU + (size_t)(d0 + tr * 4 + i) * UU + e0 + tc * 4 + j] =
                acc[i][j];
}

// ---------------- host orchestration -----------------------------------------
extern "C" void kernel_launch(void* const* d_in, const int* in_sizes, int n_in,
                              void* d_out, int out_size) {
    const float* x      = (const float*)d_in[0];
    const float* adj    = (const float*)d_in[1];
    const float* mask   = (const float*)d_in[2];
    const float* W_lin  = (const float*)d_in[3];
    const float* b_lin  = (const float*)d_in[4];
    const float* Wq_mp  = (const float*)d_in[5];
    const float* bq_mp  = (const float*)d_in[6];
    const float* Wk_mp  = (const float*)d_in[7];
    const float* bk_mp  = (const float*)d_in[8];
    const float* Wv_mp  = (const float*)d_in[9];
    const float* bv_mp  = (const float*)d_in[10];
    const float* Wk_att = (const float*)d_in[11];
    const float* Wv_att = (const float*)d_in[12];
    const float* Wq_att = (const float*)d_in[13];
    const float* Wo_att = (const float*)d_in[14];
    const float* gamma  = (const float*)d_in[15];
    const float* beta   = (const float*)d_in[16];
    const float* mean   = (const float*)d_in[17];
    const float* var    = (const float*)d_in[18];
    const float* W_proj = (const float*)d_in[19];
    const float* b_proj = (const float*)d_in[20];
    const float* W_res  = (const float*)d_in[21];
    const float* b_res  = (const float*)d_in[22];

    float *h, *q, *k, *v, *t, *y, *kv;
    cudaGetSymbolAddress((void**)&h,  g_h);
    cudaGetSymbolAddress((void**)&q,  g_q);
    cudaGetSymbolAddress((void**)&k,  g_k);
    cudaGetSymbolAddress((void**)&v,  g_v);
    cudaGetSymbolAddress((void**)&t,  g_t);
    cudaGetSymbolAddress((void**)&y,  g_y);
    cudaGetSymbolAddress((void**)&kv, g_kv);

    dim3 gg(MROWS / 128, UU / 64);

    // 1) neighbor lists from adj (recomputed every launch; deterministic)
    csr_build<<<MROWS / 8, 256>>>(adj);

    // 2) h = x @ W_lin + b_lin
    {
        Epi e = {}; e.bias = b_lin;
        gemm_k<<<gg, 256>>>(x, W_lin, h, 0, e);
    }

    // 3) q/k/v message-passing streams: 6x (spmm -> silu(gemm+bias)), mask at end
    struct Stream { float* out; const float* W; const float* b; };
    Stream st[3] = {{q, Wq_mp, bq_mp}, {k, Wk_mp, bk_mp}, {v, Wv_mp, bv_mp}};
    for (int s = 0; s < 3; s++) {
        const float* cur = h;
        for (int it = 0; it < 6; it++) {
            spmm<<<MROWS, 256>>>(cur, t);
            Epi e = {};
            e.bias = st[s].b + (it >> 1) * UU;
            e.act  = 1;
            if (it == 5) { e.maskmode = 2; e.mask = mask; }
            gemm_k<<<gg, 256>>>(t, st[s].W + (size_t)(it >> 1) * UU * UU, st[s].out, 0, e);
            cur = st[s].out;
        }
    }

    // 4) attention projections
    { Epi e = {}; e.maskmode = 1; e.mask = mask; e.act = 1;
      gemm_k<<<gg, 256>>>(k, Wk_att, h, 0, e); }          // pk -> h
    { Epi e = {}; e.maskmode = 1; e.mask = mask;
      gemm_k<<<gg, 256>>>(v, Wv_att, t, 0, e); }          // pv -> t
    { Epi e = {};
      gemm_k<<<gg, 256>>>(q, Wq_att, y, 0, e); }          // pq -> y

    // 5) kv[b] = pk^T @ pv
    kv_k<<<dim3(UU / 64, UU / 64, BB), 256>>>(h, t, kv);

    // 6) attn = pq @ kv[b]   (per-batch B matrix)
    { Epi e = {};
      gemm_k<<<gg, 256>>>(y, kv, q, 1, e); }              // attn -> q

    // 7) y = BN(attn @ Wo_att + x)
    { Epi e = {}; e.addsrc = x; e.gamma = gamma; e.beta = beta; e.mean = mean; e.var = var;
      gemm_k<<<gg, 256>>>(q, Wo_att, k, 0, e); }          // y -> k

    // 8) p = silu(y @ W_proj + b_proj)
    { Epi e = {}; e.bias = b_proj; e.act = 1;
      gemm_k<<<gg, 256>>>(k, W_proj, v, 0, e); }          // p -> v

    // 9) out = (p + x @ W_res + b_res) * mask
    { Epi e = {}; e.bias = b_res; e.addsrc = v; e.maskmode = 2; e.mask = mask;
      gemm_k<<<gg, 256>>>(x, W_res, (float*)d_out, 0, e); }
}

// round 3
// speedup vs baseline: 1.1847x; 1.1847x over previous
#include <cuda_runtime.h>
#include <cstdint>
#include <math.h>

#define BB 8
#define NN 2048
#define UU 256
#define MROWS (BB*NN)     // 16384
#define MAXNBR 128

// ---------------- device scratch ---------------------------------------------
__device__ float g_h  [MROWS*UU];
__device__ float g_y  [MROWS*UU];
__device__ float g_qkv[3*MROWS*UU];
__device__ float g_t3 [3*MROWS*UU];
__device__ float g_kv [BB*UU*UU];
__device__ int   g_cols[MROWS*MAXNBR];
__device__ int   g_cnt [MROWS];

// ---------------- tf32 helpers ------------------------------------------------
__device__ __forceinline__ void tsplit(float x, uint32_t& hi, uint32_t& lo) {
    asm("cvt.rna.tf32.f32 %0, %1;" : "=r"(hi) : "f"(x));
    float r = x - __uint_as_float(hi);
    asm("cvt.rna.tf32.f32 %0, %1;" : "=r"(lo) : "f"(r));
}

__device__ __forceinline__ void mma8(float c[4], const uint32_t a[4], const uint32_t b[2]) {
    asm volatile(
        "mma.sync.aligned.m16n8k8.row.col.f32.tf32.tf32.f32 "
        "{%0,%1,%2,%3},{%4,%5,%6,%7},{%8,%9},{%0,%1,%2,%3};"
        : "+f"(c[0]), "+f"(c[1]), "+f"(c[2]), "+f"(c[3])
        : "r"(a[0]), "r"(a[1]), "r"(a[2]), "r"(a[3]), "r"(b[0]), "r"(b[1]));
}

// ---------------- CSR build ---------------------------------------------------
__global__ void csr_build(const float* __restrict__ adj) {
    int r    = blockIdx.x * 8 + (threadIdx.x >> 5);
    int lane = threadIdx.x & 31;
    const float* row = adj + (size_t)r * NN;
    int base = 0;
    for (int c0 = 0; c0 < NN; c0 += 32) {
        float a = row[c0 + lane];
        unsigned m = __ballot_sync(0xffffffffu, a != 0.0f);
        if (a != 0.0f) {
            int pos = base + __popc(m & ((1u << lane) - 1u));
            if (pos < MAXNBR) g_cols[r * MAXNBR + pos] = c0 + lane;
        }
        base += __popc(m);
    }
    if (lane == 0) g_cnt[r] = base < MAXNBR ? base : MAXNBR;
}

// ---------------- spmm: adj @ x, multi-stream via blockIdx.x ------------------
__global__ void __launch_bounds__(256) spmm(const float* __restrict__ x,
                                            float* __restrict__ out) {
    __shared__ int cols[MAXNBR];
    int r      = blockIdx.x;
    int rr     = r & (MROWS - 1);
    int stream = r >> 14;
    int tid    = threadIdx.x;
    int cnt    = g_cnt[rr];
    for (int i = tid; i < cnt; i += 256) cols[i] = g_cols[rr * MAXNBR + i];
    __syncthreads();
    const float* xb = x + ((size_t)stream * MROWS + (size_t)(rr & ~(NN - 1))) * UU;
    float a0 = 0.f, a1 = 0.f, a2 = 0.f, a3 = 0.f;
    int j = 0;
    for (; j + 4 <= cnt; j += 4) {
        a0 += xb[cols[j + 0] * UU + tid];
        a1 += xb[cols[j + 1] * UU + tid];
        a2 += xb[cols[j + 2] * UU + tid];
        a3 += xb[cols[j + 3] * UU + tid];
    }
    for (; j < cnt; j++) a0 += xb[cols[j] * UU + tid];
    out[(size_t)r * UU + tid] = (a0 + a1) + (a2 + a3);
}

// ---------------- generic 3xTF32 GEMM  C = epi(A @ W) -------------------------
struct GemmArgs {
    const float* A;
    const float* W0; const float* W1; const float* W2;
    const float* b0; const float* b1; const float* b2;
    float* C;
    const float* addsrc;
    const float* mask;
    const float* gamma; const float* beta; const float* mean; const float* var;
    int act0, act1, act2;
    int mm0, mm1, mm2;   // maskmode: 0 none, 1 before act, 2 after act
    int ashared;         // A rows shared across streams (index r % MROWS)
    int perBatchW;       // W = W0 + (row/NN)*U*U
};

// BM=128, BN=64, BK=32, 256 threads (8 warps: 4 m x 2 n), warp tile 32x32
__global__ void __launch_bounds__(256, 2) gemm_t(GemmArgs g) {
    __shared__ float As[128][36];   // [m][k], stride 36 -> conflict-free frags
    __shared__ float Bs[32][72];    // [k][n], stride 72 -> conflict-free frags

    int tid  = threadIdx.x;
    int lane = tid & 31;
    int wid  = tid >> 5;
    int wm   = wid & 3;
    int wn   = wid >> 2;
    int row0 = blockIdx.x * 128;
    int col0 = blockIdx.y * 64;
    int stream  = blockIdx.x >> 7;          // row0 / MROWS
    int rlocal0 = row0 - stream * MROWS;

    const float* W = (stream == 0) ? g.W0 : (stream == 1 ? g.W1 : g.W2);
    if (g.perBatchW) W = g.W0 + (size_t)(rlocal0 / NN) * UU * UU;
    const float* Arow = g.A + (size_t)(g.ashared ? rlocal0 : row0) * UU;

    float acc[2][4][4];
#pragma unroll
    for (int i = 0; i < 2; i++)
#pragma unroll
        for (int j = 0; j < 4; j++)
#pragma unroll
            for (int e = 0; e < 4; e++) acc[i][j][e] = 0.f;

    int q = lane & 3, rg = lane >> 2;

    for (int k0 = 0; k0 < UU; k0 += 32) {
#pragma unroll
        for (int i = 0; i < 4; i++) {
            int idx = tid + i * 256;
            int ar = idx >> 3, kc = (idx & 7) * 4;
            *(float4*)&As[ar][kc] =
                *(const float4*)(Arow + (size_t)ar * UU + k0 + kc);
        }
#pragma unroll
        for (int i = 0; i < 2; i++) {
            int idx = tid + i * 256;
            int kr = idx >> 4, nc = (idx & 15) * 4;
            *(float4*)&Bs[kr][nc] =
                *(const float4*)(W + (size_t)(k0 + kr) * UU + col0 + nc);
        }
        __syncthreads();
#pragma unroll
        for (int ks = 0; ks < 4; ks++) {
            int kk = ks * 8;
            uint32_t ahi[2][4], alo[2][4], bhi[4][2], blo[4][2];
#pragma unroll
            for (int i = 0; i < 2; i++) {
                int rr = wm * 32 + i * 16 + rg;
                tsplit(As[rr    ][kk + q    ], ahi[i][0], alo[i][0]);
                tsplit(As[rr + 8][kk + q    ], ahi[i][1], alo[i][1]);
                tsplit(As[rr    ][kk + q + 4], ahi[i][2], alo[i][2]);
                tsplit(As[rr + 8][kk + q + 4], ahi[i][3], alo[i][3]);
            }
#pragma unroll
            for (int j = 0; j < 4; j++) {
                int nn = wn * 32 + j * 8 + rg;
                tsplit(Bs[kk + q    ][nn], bhi[j][0], blo[j][0]);
                tsplit(Bs[kk + q + 4][nn], bhi[j][1], blo[j][1]);
            }
#pragma unroll
            for (int i = 0; i < 2; i++)
#pragma unroll
                for (int j = 0; j < 4; j++) {
                    mma8(acc[i][j], alo[i], bhi[j]);
                    mma8(acc[i][j], ahi[i], blo[j]);
                    mma8(acc[i][j], ahi[i], bhi[j]);
                }
        }
        __syncthreads();
    }

    const float* bias = (stream == 0) ? g.b0 : (stream == 1 ? g.b1 : g.b2);
    int act = (stream == 0) ? g.act0 : (stream == 1 ? g.act1 : g.act2);
    int mm  = (stream == 0) ? g.mm0  : (stream == 1 ? g.mm1  : g.mm2);

#pragma unroll
    for (int i = 0; i < 2; i++) {
#pragma unroll
        for (int p = 0; p < 2; p++) {
            int roff  = wm * 32 + i * 16 + rg + p * 8;
            int rglob = row0 + roff;
            int rloc  = rlocal0 + roff;
            float mk = mm ? g.mask[rloc] : 1.f;
#pragma unroll
            for (int j = 0; j < 4; j++) {
#pragma unroll
                for (int e = 0; e < 2; e++) {
                    int cc = col0 + wn * 32 + j * 8 + q * 2 + e;
                    float v = acc[i][j][p * 2 + e];
                    if (bias)     v += bias[cc];
                    if (g.addsrc) v += g.addsrc[(size_t)rglob * UU + cc];
                    if (g.gamma)
                        v = g.gamma[cc] * (v - g.mean[cc]) * rsqrtf(g.var[cc] + 1e-3f)
                            + g.beta[cc];
                    if (mm == 1) v *= mk;
                    if (act)     v *= 1.f / (1.f + __expf(-v));
                    if (mm == 2) v *= mk;
                    g.C[(size_t)rglob * UU + cc] = v;
                }
            }
        }
    }
}

// ---------------- kv[b] = pk^T @ pv  (3xTF32, BM=64 BN=64 BK=32) --------------
__global__ void __launch_bounds__(256, 2) kv_t(const float* __restrict__ pk,
                                               const float* __restrict__ pv,
                                               float* __restrict__ kvout) {
    __shared__ float Ps[32][72];    // [k=n][m=d]
    __shared__ float Vs[32][72];    // [k=n][n=e]
    int tid  = threadIdx.x;
    int lane = tid & 31;
    int wid  = tid >> 5;
    int wm   = wid & 1;             // 2 x 4 warp grid, warp tile 32x16
    int wn   = wid >> 1;
    int d0 = blockIdx.x * 64, e0 = blockIdx.y * 64, b = blockIdx.z;
    const float* pkb = pk + (size_t)b * NN * UU;
    const float* pvb = pv + (size_t)b * NN * UU;

    float acc[2][2][4];
#pragma unroll
    for (int i = 0; i < 2; i++)
#pragma unroll
        for (int j = 0; j < 2; j++)
#pragma unroll
            for (int e = 0; e < 4; e++) acc[i][j][e] = 0.f;

    int q = lane & 3, rg = lane >> 2;

    for (int n0 = 0; n0 < NN; n0 += 32) {
#pragma unroll
        for (int i = 0; i < 2; i++) {
            int idx = tid + i * 256;
            int kr = idx >> 4, dc = (idx & 15) * 4;
            *(float4*)&Ps[kr][dc] = *(const float4*)(pkb + (size_t)(n0 + kr) * UU + d0 + dc);
            *(float4*)&Vs[kr][dc] = *(const float4*)(pvb + (size_t)(n0 + kr) * UU + e0 + dc);
        }
        __syncthreads();
#pragma unroll
        for (int ks = 0; ks < 4; ks++) {
            int kk = ks * 8;
            uint32_t ahi[2][4], alo[2][4], bhi[2][2], blo[2][2];
#pragma unroll
            for (int i = 0; i < 2; i++) {
                int rr = wm * 32 + i * 16 + rg;   // d index
                tsplit(Ps[kk + q    ][rr    ], ahi[i][0], alo[i][0]);
                tsplit(Ps[kk + q    ][rr + 8], ahi[i][1], alo[i][1]);
                tsplit(Ps[kk + q + 4][rr    ], ahi[i][2], alo[i][2]);
                tsplit(Ps[kk + q + 4][rr + 8], ahi[i][3], alo[i][3]);
            }
#pragma unroll
            for (int j = 0; j < 2; j++) {
                int nn = wn * 16 + j * 8 + rg;    // e index
                tsplit(Vs[kk + q    ][nn], bhi[j][0], blo[j][0]);
                tsplit(Vs[kk + q + 4][nn], bhi[j][1], blo[j][1]);
            }
#pragma unroll
            for (int i = 0; i < 2; i++)
#pragma unroll
                for (int j = 0; j < 2; j++) {
                    mma8(acc[i][j], alo[i], bhi[j]);
                    mma8(acc[i][j], ahi[i], blo[j]);
                    mma8(acc[i][j], ahi[i], bhi[j]);
                }
        }
        __syncthreads();
    }

    float* out = kvout + (size_t)b * UU * UU;
#pragma unroll
    for (int i = 0; i < 2; i++)
#pragma unroll
        for (int p = 0; p < 2; p++) {
            int dd = d0 + wm * 32 + i * 16 + rg + p * 8;
#pragma unroll
            for (int j = 0; j < 2; j++)
#pragma unroll
                for (int e = 0; e < 2; e++) {
                    int ee = e0 + wn * 16 + j * 8 + q * 2 + e;
                    out[(size_t)dd * UU + ee] = acc[i][j][p * 2 + e];
                }
        }
}

// ---------------- host orchestration -----------------------------------------
extern "C" void kernel_launch(void* const* d_in, const int* in_sizes, int n_in,
                              void* d_out, int out_size) {
    const float* x      = (const float*)d_in[0];
    const float* adj    = (const float*)d_in[1];
    const float* mask   = (const float*)d_in[2];
    const float* W_lin  = (const float*)d_in[3];
    const float* b_lin  = (const float*)d_in[4];
    const float* Wq_mp  = (const float*)d_in[5];
    const float* bq_mp  = (const float*)d_in[6];
    const float* Wk_mp  = (const float*)d_in[7];
    const float* bk_mp  = (const float*)d_in[8];
    const float* Wv_mp  = (const float*)d_in[9];
    const float* bv_mp  = (const float*)d_in[10];
    const float* Wk_att = (const float*)d_in[11];
    const float* Wv_att = (const float*)d_in[12];
    const float* Wq_att = (const float*)d_in[13];
    const float* Wo_att = (const float*)d_in[14];
    const float* gamma  = (const float*)d_in[15];
    const float* beta   = (const float*)d_in[16];
    const float* mean   = (const float*)d_in[17];
    const float* var    = (const float*)d_in[18];
    const float* W_proj = (const float*)d_in[19];
    const float* b_proj = (const float*)d_in[20];
    const float* W_res  = (const float*)d_in[21];
    const float* b_res  = (const float*)d_in[22];

    float *h, *y, *qkv, *t3, *kv;
    cudaGetSymbolAddress((void**)&h,   g_h);
    cudaGetSymbolAddress((void**)&y,   g_y);
    cudaGetSymbolAddress((void**)&qkv, g_qkv);
    cudaGetSymbolAddress((void**)&t3,  g_t3);
    cudaGetSymbolAddress((void**)&kv,  g_kv);

    dim3 g1(MROWS / 128, UU / 64);       // 512 blocks
    dim3 g3(3 * MROWS / 128, UU / 64);   // 1536 blocks

    csr_build<<<MROWS / 8, 256>>>(adj);

    // h = x @ W_lin + b_lin
    { GemmArgs a = {}; a.A = x; a.W0 = W_lin; a.b0 = b_lin; a.C = h;
      gemm_t<<<g1, 256>>>(a); }

    // mp iteration 0: adj@h shared by all three streams
    spmm<<<MROWS, 256>>>(h, t3);
    { GemmArgs a = {}; a.A = t3; a.ashared = 1;
      a.W0 = Wq_mp; a.W1 = Wk_mp; a.W2 = Wv_mp;
      a.b0 = bq_mp; a.b1 = bk_mp; a.b2 = bv_mp;
      a.act0 = a.act1 = a.act2 = 1; a.C = qkv;
      gemm_t<<<g3, 256>>>(a); }

    // mp iterations 1..5 (fused q/k/v streams)
    for (int it = 1; it < 6; it++) {
        int i = it >> 1;
        spmm<<<3 * MROWS, 256>>>(qkv, t3);
        GemmArgs a = {}; a.A = t3;
        a.W0 = Wq_mp + (size_t)i * UU * UU;
        a.W1 = Wk_mp + (size_t)i * UU * UU;
        a.W2 = Wv_mp + (size_t)i * UU * UU;
        a.b0 = bq_mp + i * UU; a.b1 = bk_mp + i * UU; a.b2 = bv_mp + i * UU;
        a.act0 = a.act1 = a.act2 = 1;
        if (it == 5) { a.mm0 = a.mm1 = a.mm2 = 2; a.mask = mask; }
        a.C = qkv;
        gemm_t<<<g3, 256>>>(a);
    }

    // attention projections: pq = q@Wq ; pk = silu((k@Wk)*m) ; pv = (v@Wv)*m
    { GemmArgs a = {}; a.A = qkv;
      a.W0 = Wq_att; a.W1 = Wk_att; a.W2 = Wv_att;
      a.act1 = 1; a.mm1 = 1; a.mm2 = 1; a.mask = mask;
      a.C = t3;
      gemm_t<<<g3, 256>>>(a); }

    // kv[b] = pk^T @ pv
    kv_t<<<dim3(UU / 64, UU / 64, BB), 256>>>(t3 + (size_t)MROWS * UU,
                                              t3 + (size_t)2 * MROWS * UU, kv);

    // attn = pq @ kv[b]
    { GemmArgs a = {}; a.A = t3; a.W0 = kv; a.perBatchW = 1; a.C = h;
      gemm_t<<<g1, 256>>>(a); }

    // y = BN(attn @ Wo + x)
    { GemmArgs a = {}; a.A = h; a.W0 = Wo_att; a.addsrc = x;
      a.gamma = gamma; a.beta = beta; a.mean = mean; a.var = var; a.C = y;
      gemm_t<<<g1, 256>>>(a); }

    // p = silu(y @ W_proj + b_proj)
    { GemmArgs a = {}; a.A = y; a.W0 = W_proj; a.b0 = b_proj; a.act0 = 1; a.C = t3;
      gemm_t<<<g1, 256>>>(a); }

    // out = (p + x @ W_res + b_res) * mask
    { GemmArgs a = {}; a.A = x; a.W0 = W_res; a.b0 = b_res; a.addsrc = t3;
      a.mm0 = 2; a.mask = mask; a.C = (float*)d_out;
      gemm_t<<<g1, 256>>>(a); }
}

// round 5
// speedup vs baseline: 1.2353x; 1.0427x over previous
#include <cuda_runtime.h>
#include <cstdint>
#include <math.h>

#define BB 8
#define NN 2048
#define UU 256
#define MROWS (BB*NN)     // 16384
#define MAXNBR 128

// ---------------- device scratch ---------------------------------------------
__device__ float g_h  [MROWS*UU];
__device__ float g_y  [MROWS*UU];
__device__ float g_qkv[3*MROWS*UU];
__device__ float g_t3 [3*MROWS*UU];
__device__ float g_kv [BB*UU*UU];
__device__ int   g_cols[MROWS*MAXNBR];
__device__ int   g_cnt [MROWS];

// ---------------- tf32 helpers ------------------------------------------------
__device__ __forceinline__ void tsplit(float x, uint32_t& hi, uint32_t& lo) {
    asm("cvt.rna.tf32.f32 %0, %1;" : "=r"(hi) : "f"(x));
    float r = x - __uint_as_float(hi);
    asm("cvt.rna.tf32.f32 %0, %1;" : "=r"(lo) : "f"(r));
}

__device__ __forceinline__ void mma8(float c[4], const uint32_t a[4], const uint32_t b[2]) {
    asm volatile(
        "mma.sync.aligned.m16n8k8.row.col.f32.tf32.tf32.f32 "
        "{%0,%1,%2,%3},{%4,%5,%6,%7},{%8,%9},{%0,%1,%2,%3};"
        : "+f"(c[0]), "+f"(c[1]), "+f"(c[2]), "+f"(c[3])
        : "r"(a[0]), "r"(a[1]), "r"(a[2]), "r"(a[3]), "r"(b[0]), "r"(b[1]));
}

// ---------------- CSR build: float4 + warp scan -------------------------------
__global__ void csr_build(const float* __restrict__ adj) {
    int r    = blockIdx.x * 8 + (threadIdx.x >> 5);
    int lane = threadIdx.x & 31;
    const float4* row = (const float4*)(adj + (size_t)r * NN);
    int base = 0;
    for (int c0 = 0; c0 < NN / 4; c0 += 32) {
        float4 v = row[c0 + lane];
        unsigned m4 = (v.x != 0.f ? 1u : 0u) | (v.y != 0.f ? 2u : 0u)
                    | (v.z != 0.f ? 4u : 0u) | (v.w != 0.f ? 8u : 0u);
        int cnt4 = __popc(m4);
        int inc = cnt4;
#pragma unroll
        for (int o = 1; o < 32; o <<= 1) {
            int t = __shfl_up_sync(0xffffffffu, inc, o);
            if (lane >= o) inc += t;
        }
        int pos = base + inc - cnt4;
        int colbase = (c0 + lane) * 4;
        if (m4 & 1) { if (pos < MAXNBR) g_cols[r * MAXNBR + pos] = colbase;     pos++; }
        if (m4 & 2) { if (pos < MAXNBR) g_cols[r * MAXNBR + pos] = colbase + 1; pos++; }
        if (m4 & 4) { if (pos < MAXNBR) g_cols[r * MAXNBR + pos] = colbase + 2; pos++; }
        if (m4 & 8) { if (pos < MAXNBR) g_cols[r * MAXNBR + pos] = colbase + 3; pos++; }
        base += __shfl_sync(0xffffffffu, inc, 31);
    }
    if (lane == 0) g_cnt[r] = base < MAXNBR ? base : MAXNBR;
}

// ---------------- spmm: adj @ x, float4, 4 rows/block -------------------------
__global__ void __launch_bounds__(256) spmm(const float* __restrict__ x,
                                            float* __restrict__ out) {
    __shared__ int cols[4][MAXNBR];
    int sub = threadIdx.x >> 6;         // row within block
    int t   = threadIdx.x & 63;         // 64 threads * float4 = 256 floats
    int r      = blockIdx.x * 4 + sub;
    int rr     = r & (MROWS - 1);
    int stream = r >> 14;
    int cnt = g_cnt[rr];
    for (int i = t; i < cnt; i += 64) cols[sub][i] = g_cols[rr * MAXNBR + i];
    __syncthreads();
    const float* xb = x + ((size_t)stream * MROWS + (size_t)(rr & ~(NN - 1))) * UU;
    float4 s0 = {0,0,0,0}, s1 = {0,0,0,0};
    int j = 0;
    for (; j + 2 <= cnt; j += 2) {
        float4 v0 = *((const float4*)(xb + (size_t)cols[sub][j]     * UU) + t);
        float4 v1 = *((const float4*)(xb + (size_t)cols[sub][j + 1] * UU) + t);
        s0.x += v0.x; s0.y += v0.y; s0.z += v0.z; s0.w += v0.w;
        s1.x += v1.x; s1.y += v1.y; s1.z += v1.z; s1.w += v1.w;
    }
    if (j < cnt) {
        float4 v0 = *((const float4*)(xb + (size_t)cols[sub][j] * UU) + t);
        s0.x += v0.x; s0.y += v0.y; s0.z += v0.z; s0.w += v0.w;
    }
    float4 o = {s0.x + s1.x, s0.y + s1.y, s0.z + s1.z, s0.w + s1.w};
    *((float4*)(out + (size_t)r * UU) + t) = o;
}

// ---------------- generic 3xTF32 GEMM  C = epi(A @ W) -------------------------
// Pre-split (hi,lo) tf32 pairs stored interleaved in shared memory as uint2.
struct GemmArgs {
    const float* A;
    const float* W0; const float* W1; const float* W2;
    const float* b0; const float* b1; const float* b2;
    float* C;
    const float* addsrc;
    const float* mask;
    const float* gamma; const float* beta; const float* mean; const float* var;
    int act0, act1, act2;
    int mm0, mm1, mm2;   // maskmode: 0 none, 1 before act, 2 after act
    int ashared;         // A rows shared across streams (index r % MROWS)
    int perBatchW;       // W = W0 + (row/NN)*U*U
};

#define AS_STRIDE 36     // uint2 units; 36 % 16 == 4 -> conflict-free frags
#define BS_STRIDE 68     // 68 % 16 == 4
#define SMEM_GEMM ((128*AS_STRIDE + 32*BS_STRIDE) * (int)sizeof(uint2))

// BM=128, BN=64, BK=32, 256 threads (8 warps: 4 m x 2 n), warp tile 32x32
__global__ void __launch_bounds__(256, 2) gemm_t(GemmArgs g) {
    extern __shared__ __align__(16) uint2 sm[];
    uint2 (*As)[AS_STRIDE] = (uint2(*)[AS_STRIDE])sm;               // [m][k]
    uint2 (*Bs)[BS_STRIDE] = (uint2(*)[BS_STRIDE])(sm + 128 * AS_STRIDE); // [k][n]

    int tid  = threadIdx.x;
    int lane = tid & 31;
    int wid  = tid >> 5;
    int wm   = wid & 3;
    int wn   = wid >> 2;
    int row0 = blockIdx.x * 128;
    int col0 = blockIdx.y * 64;
    int stream  = blockIdx.x >> 7;
    int rlocal0 = row0 - stream * MROWS;

    const float* W = (stream == 0) ? g.W0 : (stream == 1 ? g.W1 : g.W2);
    if (g.perBatchW) W = g.W0 + (size_t)(rlocal0 / NN) * UU * UU;
    const float* Arow = g.A + (size_t)(g.ashared ? rlocal0 : row0) * UU;

    float acc[2][4][4];
#pragma unroll
    for (int i = 0; i < 2; i++)
#pragma unroll
        for (int j = 0; j < 4; j++)
#pragma unroll
            for (int e = 0; e < 4; e++) acc[i][j][e] = 0.f;

    int q = lane & 3, rg = lane >> 2;

    for (int k0 = 0; k0 < UU; k0 += 32) {
        // fill A: 128x32, split once per element
#pragma unroll
        for (int i = 0; i < 4; i++) {
            int idx = tid + i * 256;
            int ar = idx >> 3, kc = (idx & 7) * 4;
            float4 vv = *(const float4*)(Arow + (size_t)ar * UU + k0 + kc);
            uint32_t h0, l0, h1, l1, h2, l2, h3, l3;
            tsplit(vv.x, h0, l0); tsplit(vv.y, h1, l1);
            tsplit(vv.z, h2, l2); tsplit(vv.w, h3, l3);
            *(uint4*)&As[ar][kc]     = make_uint4(h0, l0, h1, l1);
            *(uint4*)&As[ar][kc + 2] = make_uint4(h2, l2, h3, l3);
        }
        // fill B: 32x64
#pragma unroll
        for (int i = 0; i < 2; i++) {
            int idx = tid + i * 256;
            int kr = idx >> 4, nc = (idx & 15) * 4;
            float4 vv = *(const float4*)(W + (size_t)(k0 + kr) * UU + col0 + nc);
            uint32_t h0, l0, h1, l1, h2, l2, h3, l3;
            tsplit(vv.x, h0, l0); tsplit(vv.y, h1, l1);
            tsplit(vv.z, h2, l2); tsplit(vv.w, h3, l3);
            *(uint4*)&Bs[kr][nc]     = make_uint4(h0, l0, h1, l1);
            *(uint4*)&Bs[kr][nc + 2] = make_uint4(h2, l2, h3, l3);
        }
        __syncthreads();
#pragma unroll
        for (int ks = 0; ks < 4; ks++) {
            int kk = ks * 8;
            uint32_t ahi[2][4], alo[2][4], bhi[4][2], blo[4][2];
#pragma unroll
            for (int i = 0; i < 2; i++) {
                int rr = wm * 32 + i * 16 + rg;
                uint2 a0 = As[rr    ][kk + q];
                uint2 a1 = As[rr + 8][kk + q];
                uint2 a2 = As[rr    ][kk + q + 4];
                uint2 a3 = As[rr + 8][kk + q + 4];
                ahi[i][0] = a0.x; alo[i][0] = a0.y;
                ahi[i][1] = a1.x; alo[i][1] = a1.y;
                ahi[i][2] = a2.x; alo[i][2] = a2.y;
                ahi[i][3] = a3.x; alo[i][3] = a3.y;
            }
#pragma unroll
            for (int j = 0; j < 4; j++) {
                int nn = wn * 32 + j * 8 + rg;
                uint2 b0 = Bs[kk + q    ][nn];
                uint2 b1 = Bs[kk + q + 4][nn];
                bhi[j][0] = b0.x; blo[j][0] = b0.y;
                bhi[j][1] = b1.x; blo[j][1] = b1.y;
            }
#pragma unroll
            for (int i = 0; i < 2; i++)
#pragma unroll
                for (int j = 0; j < 4; j++) {
                    mma8(acc[i][j], alo[i], bhi[j]);
                    mma8(acc[i][j], ahi[i], blo[j]);
                    mma8(acc[i][j], ahi[i], bhi[j]);
                }
        }
        __syncthreads();
    }

    const float* bias = (stream == 0) ? g.b0 : (stream == 1 ? g.b1 : g.b2);
    int act = (stream == 0) ? g.act0 : (stream == 1 ? g.act1 : g.act2);
    int mm  = (stream == 0) ? g.mm0  : (stream == 1 ? g.mm1  : g.mm2);

#pragma unroll
    for (int i = 0; i < 2; i++) {
#pragma unroll
        for (int p = 0; p < 2; p++) {
            int roff  = wm * 32 + i * 16 + rg + p * 8;
            int rglob = row0 + roff;
            int rloc  = rlocal0 + roff;
            float mk = mm ? g.mask[rloc] : 1.f;
#pragma unroll
            for (int j = 0; j < 4; j++) {
#pragma unroll
                for (int e = 0; e < 2; e++) {
                    int cc = col0 + wn * 32 + j * 8 + q * 2 + e;
                    float v = acc[i][j][p * 2 + e];
                    if (bias)     v += bias[cc];
                    if (g.addsrc) v += g.addsrc[(size_t)rglob * UU + cc];
                    if (g.gamma)
                        v = g.gamma[cc] * (v - g.mean[cc]) * rsqrtf(g.var[cc] + 1e-3f)
                            + g.beta[cc];
                    if (mm == 1) v *= mk;
                    if (act)     v *= 1.f / (1.f + __expf(-v));
                    if (mm == 2) v *= mk;
                    g.C[(size_t)rglob * UU + cc] = v;
                }
            }
        }
    }
}

// ---------------- kv[b] = pk^T @ pv  (3xTF32, BM=64 BN=64 BK=32) --------------
__global__ void __launch_bounds__(256, 2) kv_t(const float* __restrict__ pk,
                                               const float* __restrict__ pv,
                                               float* __restrict__ kvout) {
    __shared__ float Ps[32][72];    // [k=n][m=d]
    __shared__ float Vs[32][72];    // [k=n][n=e]
    int tid  = threadIdx.x;
    int lane = tid & 31;
    int wid  = tid >> 5;
    int wm   = wid & 1;
    int wn   = wid >> 1;
    int d0 = blockIdx.x * 64, e0 = blockIdx.y * 64, b = blockIdx.z;
    const float* pkb = pk + (size_t)b * NN * UU;
    const float* pvb = pv + (size_t)b * NN * UU;

    float acc[2][2][4];
#pragma unroll
    for (int i = 0; i < 2; i++)
#pragma unroll
        for (int j = 0; j < 2; j++)
#pragma unroll
            for (int e = 0; e < 4; e++) acc[i][j][e] = 0.f;

    int q = lane & 3, rg = lane >> 2;

    for (int n0 = 0; n0 < NN; n0 += 32) {
#pragma unroll
        for (int i = 0; i < 2; i++) {
            int idx = tid + i * 256;
            int kr = idx >> 4, dc = (idx & 15) * 4;
            *(float4*)&Ps[kr][dc] = *(const float4*)(pkb + (size_t)(n0 + kr) * UU + d0 + dc);
            *(float4*)&Vs[kr][dc] = *(const float4*)(pvb + (size_t)(n0 + kr) * UU + e0 + dc);
        }
        __syncthreads();
#pragma unroll
        for (int ks = 0; ks < 4; ks++) {
            int kk = ks * 8;
            uint32_t ahi[2][4], alo[2][4], bhi[2][2], blo[2][2];
#pragma unroll
            for (int i = 0; i < 2; i++) {
                int rr = wm * 32 + i * 16 + rg;
                tsplit(Ps[kk + q    ][rr    ], ahi[i][0], alo[i][0]);
                tsplit(Ps[kk + q    ][rr + 8], ahi[i][1], alo[i][1]);
                tsplit(Ps[kk + q + 4][rr    ], ahi[i][2], alo[i][2]);
                tsplit(Ps[kk + q + 4][rr + 8], ahi[i][3], alo[i][3]);
            }
#pragma unroll
            for (int j = 0; j < 2; j++) {
                int nn = wn * 16 + j * 8 + rg;
                tsplit(Vs[kk + q    ][nn], bhi[j][0], blo[j][0]);
                tsplit(Vs[kk + q + 4][nn], bhi[j][1], blo[j][1]);
            }
#pragma unroll
            for (int i = 0; i < 2; i++)
#pragma unroll
                for (int j = 0; j < 2; j++) {
                    mma8(acc[i][j], alo[i], bhi[j]);
                    mma8(acc[i][j], ahi[i], blo[j]);
                    mma8(acc[i][j], ahi[i], bhi[j]);
                }
        }
        __syncthreads();
    }

    float* out = kvout + (size_t)b * UU * UU;
#pragma unroll
    for (int i = 0; i < 2; i++)
#pragma unroll
        for (int p = 0; p < 2; p++) {
            int dd = d0 + wm * 32 + i * 16 + rg + p * 8;
#pragma unroll
            for (int j = 0; j < 2; j++)
#pragma unroll
                for (int e = 0; e < 2; e++) {
                    int ee = e0 + wn * 16 + j * 8 + q * 2 + e;
                    out[(size_t)dd * UU + ee] = acc[i][j][p * 2 + e];
                }
        }
}

// ---------------- host orchestration -----------------------------------------
extern "C" void kernel_launch(void* const* d_in, const int* in_sizes, int n_in,
                              void* d_out, int out_size) {
    const float* x      = (const float*)d_in[0];
    const float* adj    = (const float*)d_in[1];
    const float* mask   = (const float*)d_in[2];
    const float* W_lin  = (const float*)d_in[3];
    const float* b_lin  = (const float*)d_in[4];
    const float* Wq_mp  = (const float*)d_in[5];
    const float* bq_mp  = (const float*)d_in[6];
    const float* Wk_mp  = (const float*)d_in[7];
    const float* bk_mp  = (const float*)d_in[8];
    const float* Wv_mp  = (const float*)d_in[9];
    const float* bv_mp  = (const float*)d_in[10];
    const float* Wk_att = (const float*)d_in[11];
    const float* Wv_att = (const float*)d_in[12];
    const float* Wq_att = (const float*)d_in[13];
    const float* Wo_att = (const float*)d_in[14];
    const float* gamma  = (const float*)d_in[15];
    const float* beta   = (const float*)d_in[16];
    const float* mean   = (const float*)d_in[17];
    const float* var    = (const float*)d_in[18];
    const float* W_proj = (const float*)d_in[19];
    const float* b_proj = (const float*)d_in[20];
    const float* W_res  = (const float*)d_in[21];
    const float* b_res  = (const float*)d_in[22];

    float *h, *y, *qkv, *t3, *kv;
    cudaGetSymbolAddress((void**)&h,   g_h);
    cudaGetSymbolAddress((void**)&y,   g_y);
    cudaGetSymbolAddress((void**)&qkv, g_qkv);
    cudaGetSymbolAddress((void**)&t3,  g_t3);
    cudaGetSymbolAddress((void**)&kv,  g_kv);

    cudaFuncSetAttribute(gemm_t, cudaFuncAttributeMaxDynamicSharedMemorySize, SMEM_GEMM);

    dim3 g1(MROWS / 128, UU / 64);       // 512 blocks
    dim3 g3(3 * MROWS / 128, UU / 64);   // 1536 blocks

    csr_build<<<MROWS / 8, 256>>>(adj);

    // h = x @ W_lin + b_lin
    { GemmArgs a = {}; a.A = x; a.W0 = W_lin; a.b0 = b_lin; a.C = h;
      gemm_t<<<g1, 256, SMEM_GEMM>>>(a); }

    // mp iteration 0: adj@h shared by all three streams
    spmm<<<MROWS / 4, 256>>>(h, t3);
    { GemmArgs a = {}; a.A = t3; a.ashared = 1;
      a.W0 = Wq_mp; a.W1 = Wk_mp; a.W2 = Wv_mp;
      a.b0 = bq_mp; a.b1 = bk_mp; a.b2 = bv_mp;
      a.act0 = a.act1 = a.act2 = 1; a.C = qkv;
      gemm_t<<<g3, 256, SMEM_GEMM>>>(a); }

    // mp iterations 1..5 (fused q/k/v streams)
    for (int it = 1; it < 6; it++) {
        int i = it >> 1;
        spmm<<<3 * MROWS / 4, 256>>>(qkv, t3);
        GemmArgs a = {}; a.A = t3;
        a.W0 = Wq_mp + (size_t)i * UU * UU;
        a.W1 = Wk_mp + (size_t)i * UU * UU;
        a.W2 = Wv_mp + (size_t)i * UU * UU;
        a.b0 = bq_mp + i * UU; a.b1 = bk_mp + i * UU; a.b2 = bv_mp + i * UU;
        a.act0 = a.act1 = a.act2 = 1;
        if (it == 5) { a.mm0 = a.mm1 = a.mm2 = 2; a.mask = mask; }
        a.C = qkv;
        gemm_t<<<g3, 256, SMEM_GEMM>>>(a);
    }

    // attention projections: pq = q@Wq ; pk = silu((k@Wk)*m) ; pv = (v@Wv)*m
    { GemmArgs a = {}; a.A = qkv;
      a.W0 = Wq_att; a.W1 = Wk_att; a.W2 = Wv_att;
      a.act1 = 1; a.mm1 = 1; a.mm2 = 1; a.mask = mask;
      a.C = t3;
      gemm_t<<<g3, 256, SMEM_GEMM>>>(a); }

    // kv[b] = pk^T @ pv
    kv_t<<<dim3(UU / 64, UU / 64, BB), 256>>>(t3 + (size_t)MROWS * UU,
                                              t3 + (size_t)2 * MROWS * UU, kv);

    // attn = pq @ kv[b]
    { GemmArgs a = {}; a.A = t3; a.W0 = kv; a.perBatchW = 1; a.C = h;
      gemm_t<<<g1, 256, SMEM_GEMM>>>(a); }

    // y = BN(attn @ Wo + x)
    { GemmArgs a = {}; a.A = h; a.W0 = Wo_att; a.addsrc = x;
      a.gamma = gamma; a.beta = beta; a.mean = mean; a.var = var; a.C = y;
      gemm_t<<<g1, 256, SMEM_GEMM>>>(a); }

    // p = silu(y @ W_proj + b_proj)
    { GemmArgs a = {}; a.A = y; a.W0 = W_proj; a.b0 = b_proj; a.act0 = 1; a.C = t3;
      gemm_t<<<g1, 256, SMEM_GEMM>>>(a); }

    // out = (p + x @ W_res + b_res) * mask
    { GemmArgs a = {}; a.A = x; a.W0 = W_res; a.b0 = b_res; a.addsrc = t3;
      a.mm0 = 2; a.mask = mask; a.C = (float*)d_out;
      gemm_t<<<g1, 256, SMEM_GEMM>>>(a); }
}

// round 10
// speedup vs baseline: 1.3243x; 1.0720x over previous
#include <cuda_runtime.h>
#include <cstdint>
#include <math.h>

#define BB 8
#define NN 2048
#define UU 256
#define MROWS (BB*NN)     // 16384
#define MAXNBR 128

// ---------------- device scratch ---------------------------------------------
__device__ float g_h  [MROWS*UU];
__device__ float g_y  [MROWS*UU];
__device__ float g_qkv[3*MROWS*UU];
__device__ float g_t3 [3*MROWS*UU];
__device__ uint4 g_kvp[BB*32*4*256];    // packed kv planes per batch (4MB)
__device__ uint4 g_wp [16*32*4*256];    // packed split weights (8MB)
__device__ int   g_cols[MROWS*MAXNBR];
__device__ int   g_cnt [MROWS];

// ---------------- helpers -----------------------------------------------------
__device__ __forceinline__ void tsplit(float x, uint32_t& hi, uint32_t& lo) {
    asm("cvt.rna.tf32.f32 %0, %1;" : "=r"(hi) : "f"(x));
    float r = x - __uint_as_float(hi);
    asm("cvt.rna.tf32.f32 %0, %1;" : "=r"(lo) : "f"(r));
}
__device__ __forceinline__ void mma8(float c[4], const uint32_t a[4], const uint32_t b[2]) {
    asm volatile(
        "mma.sync.aligned.m16n8k8.row.col.f32.tf32.tf32.f32 "
        "{%0,%1,%2,%3},{%4,%5,%6,%7},{%8,%9},{%0,%1,%2,%3};"
        : "+f"(c[0]), "+f"(c[1]), "+f"(c[2]), "+f"(c[3])
        : "r"(a[0]), "r"(a[1]), "r"(a[2]), "r"(a[3]), "r"(b[0]), "r"(b[1]));
}
__device__ __forceinline__ uint32_t smem_u32(const void* p) {
    uint32_t a;
    asm("{ .reg .u64 t; cvta.to.shared.u64 t, %1; cvt.u32.u64 %0, t; }" : "=r"(a) : "l"(p));
    return a;
}
#define CP_ASYNC16(dst, src) \
    asm volatile("cp.async.cg.shared.global [%0], [%1], 16;" :: "r"(dst), "l"(src))
#define CP_COMMIT()  asm volatile("cp.async.commit_group;" ::: "memory")
#define CP_WAIT0()   asm volatile("cp.async.wait_group 0;" ::: "memory")

// ---------------- weight pack: split W[k][n] into fragment-major planes -------
// cell(ksg, q, n) = {hi(W[8ksg+q][n]), lo, hi(W[8ksg+q+4][n]), lo}
struct WTptrs { const float* src[16]; };
__global__ void pack_w(WTptrs p, uint4* __restrict__ dst) {
    int m = blockIdx.y;
    int c = blockIdx.x * 256 + threadIdx.x;      // 0..32767
    int n   = c & 255;
    int q   = (c >> 8) & 3;
    int ksg = c >> 10;
    const float* S = p.src[m];
    float v0 = S[(size_t)(8 * ksg + q) * UU + n];
    float v1 = S[(size_t)(8 * ksg + q + 4) * UU + n];
    uint32_t h0, l0, h1, l1;
    tsplit(v0, h0, l0); tsplit(v1, h1, l1);
    dst[(size_t)m * 32768 + c] = make_uint4(h0, l0, h1, l1);
}

// ---------------- CSR build: float4 + warp scan -------------------------------
__global__ void csr_build(const float* __restrict__ adj) {
    int r    = blockIdx.x * 8 + (threadIdx.x >> 5);
    int lane = threadIdx.x & 31;
    const float4* row = (const float4*)(adj + (size_t)r * NN);
    int base = 0;
    for (int c0 = 0; c0 < NN / 4; c0 += 32) {
        float4 v = row[c0 + lane];
        unsigned m4 = (v.x != 0.f ? 1u : 0u) | (v.y != 0.f ? 2u : 0u)
                    | (v.z != 0.f ? 4u : 0u) | (v.w != 0.f ? 8u : 0u);
        int cnt4 = __popc(m4);
        int inc = cnt4;
#pragma unroll
        for (int o = 1; o < 32; o <<= 1) {
            int t = __shfl_up_sync(0xffffffffu, inc, o);
            if (lane >= o) inc += t;
        }
        int pos = base + inc - cnt4;
        int colbase = (c0 + lane) * 4;
        if (m4 & 1) { if (pos < MAXNBR) g_cols[r * MAXNBR + pos] = colbase;     pos++; }
        if (m4 & 2) { if (pos < MAXNBR) g_cols[r * MAXNBR + pos] = colbase + 1; pos++; }
        if (m4 & 4) { if (pos < MAXNBR) g_cols[r * MAXNBR + pos] = colbase + 2; pos++; }
        if (m4 & 8) { if (pos < MAXNBR) g_cols[r * MAXNBR + pos] = colbase + 3; pos++; }
        base += __shfl_sync(0xffffffffu, inc, 31);
    }
    if (lane == 0) g_cnt[r] = base < MAXNBR ? base : MAXNBR;
}

// ---------------- spmm: adj @ x, float4, 4 rows/block -------------------------
__global__ void __launch_bounds__(256) spmm(const float* __restrict__ x,
                                            float* __restrict__ out) {
    __shared__ int cols[4][MAXNBR];
    int sub = threadIdx.x >> 6;
    int t   = threadIdx.x & 63;
    int r      = blockIdx.x * 4 + sub;
    int rr     = r & (MROWS - 1);
    int stream = r >> 14;
    int cnt = g_cnt[rr];
    for (int i = t; i < cnt; i += 64) cols[sub][i] = g_cols[rr * MAXNBR + i];
    __syncthreads();
    const float* xb = x + ((size_t)stream * MROWS + (size_t)(rr & ~(NN - 1))) * UU;
    float4 s0 = {0,0,0,0}, s1 = {0,0,0,0};
    int j = 0;
    for (; j + 2 <= cnt; j += 2) {
        float4 v0 = *((const float4*)(xb + (size_t)cols[sub][j]     * UU) + t);
        float4 v1 = *((const float4*)(xb + (size_t)cols[sub][j + 1] * UU) + t);
        s0.x += v0.x; s0.y += v0.y; s0.z += v0.z; s0.w += v0.w;
        s1.x += v1.x; s1.y += v1.y; s1.z += v1.z; s1.w += v1.w;
    }
    if (j < cnt) {
        float4 v0 = *((const float4*)(xb + (size_t)cols[sub][j] * UU) + t);
        s0.x += v0.x; s0.y += v0.y; s0.z += v0.z; s0.w += v0.w;
    }
    float4 o = {s0.x + s1.x, s0.y + s1.y, s0.z + s1.z, s0.w + s1.w};
    *((float4*)(out + (size_t)r * UU) + t) = o;
}

// ---------------- 3xTF32 GEMM, fragment-major packed smem ---------------------
// A: [4 ks][4 q][128 r] uint4 cells, row stride 130 u4, ks stride 522 u4.
// B: [4 ks][4 q][ 64 n] uint4 cells, row stride  66 u4, ks stride 266 u4.
struct GemmArgs {
    const float* A;
    const uint4* W0; const uint4* W1; const uint4* W2;   // packed weights
    const float* b0; const float* b1; const float* b2;
    float* C;
    const float* addsrc;
    const float* mask;
    const float* gamma; const float* beta; const float* mean; const float* var;
    int act0, act1, act2;
    int mm0, mm1, mm2;   // 0 none, 1 before act, 2 after act
    int ashared;
    int perBatchW;
};

#define A_U4   2088               // 4*522
#define B_U4   1064               // 4*266
#define SMEM_G ((A_U4 + B_U4) * 16)

__global__ void __launch_bounds__(256, 2) gemm6(GemmArgs g) {
    extern __shared__ __align__(16) uint4 sm4[];
    uint4* Asm = sm4;
    uint4* Bsm = sm4 + A_U4;

    int tid  = threadIdx.x;
    int lane = tid & 31;
    int wid  = tid >> 5;
    int wm   = wid & 3;
    int wn   = wid >> 2;
    int q    = lane & 3;
    int rg   = lane >> 2;
    int row0 = blockIdx.x * 128;
    int col0 = blockIdx.y * 64;
    int stream  = blockIdx.x >> 7;
    int rlocal0 = row0 - stream * MROWS;

    const uint4* W = (stream == 0) ? g.W0 : (stream == 1 ? g.W1 : g.W2);
    if (g.perBatchW) W = g.W0 + (size_t)(rlocal0 / NN) * 32768;
    const float* Arow = g.A + (size_t)(g.ashared ? rlocal0 : row0) * UU;

    // fill task decomposition (constant across k0)
    int fA_ks = tid & 3,  fA_r = tid >> 2;          // + 64 rows on second pass
    int fB_n  = tid & 63, fB_q = (tid >> 6) & 3;    // ksl = pass
    int aoff  = q * 130 + wm * 32 + rg;             // frag base (uint4 idx)
    int boff  = q * 66  + wn * 32 + rg;

    float acc[2][4][4];
#pragma unroll
    for (int i = 0; i < 2; i++)
#pragma unroll
        for (int j = 0; j < 4; j++)
#pragma unroll
            for (int e = 0; e < 4; e++) acc[i][j][e] = 0.f;

    for (int k0 = 0; k0 < UU; k0 += 32) {
        if (k0) __syncthreads();   // previous iter's frag reads complete

        // B tile: pure cp.async from packed weights
        const uint4* wsrc = W + (size_t)(k0 >> 3) * 1024 + fB_q * 256 + col0 + fB_n;
        uint4* bdst = Bsm + fB_q * 66 + fB_n;
#pragma unroll
        for (int ksl = 0; ksl < 4; ksl++)
            CP_ASYNC16(smem_u32(bdst + ksl * 266), wsrc + ksl * 1024);
        CP_COMMIT();

        // A tile: load 8 consecutive k, split, store packed cells
#pragma unroll
        for (int t = 0; t < 2; t++) {
            int r = fA_r + t * 64;
            const float4* s = (const float4*)(Arow + (size_t)r * UU + k0 + fA_ks * 8);
            float4 v0 = s[0], v1 = s[1];
            uint32_t h0,l0,h1,l1,h2,l2,h3,l3,h4,l4,h5,l5,h6,l6,h7,l7;
            tsplit(v0.x,h0,l0); tsplit(v0.y,h1,l1); tsplit(v0.z,h2,l2); tsplit(v0.w,h3,l3);
            tsplit(v1.x,h4,l4); tsplit(v1.y,h5,l5); tsplit(v1.z,h6,l6); tsplit(v1.w,h7,l7);
            uint4* ab = Asm + fA_ks * 522 + r;
            ab[0 * 130] = make_uint4(h0, l0, h4, l4);
            ab[1 * 130] = make_uint4(h1, l1, h5, l5);
            ab[2 * 130] = make_uint4(h2, l2, h6, l6);
            ab[3 * 130] = make_uint4(h3, l3, h7, l7);
        }
        CP_WAIT0();
        __syncthreads();

#pragma unroll
        for (int ks = 0; ks < 4; ks++) {
            uint32_t ahi[2][4], alo[2][4], bhi[4][2], blo[4][2];
            const uint4* ap = Asm + ks * 522 + aoff;
            const uint4* bp = Bsm + ks * 266 + boff;
#pragma unroll
            for (int i = 0; i < 2; i++) {
                uint4 c0 = ap[i * 16];
                uint4 c1 = ap[i * 16 + 8];
                ahi[i][0] = c0.x; alo[i][0] = c0.y;
                ahi[i][2] = c0.z; alo[i][2] = c0.w;
                ahi[i][1] = c1.x; alo[i][1] = c1.y;
                ahi[i][3] = c1.z; alo[i][3] = c1.w;
            }
#pragma unroll
            for (int j = 0; j < 4; j++) {
                uint4 b = bp[j * 8];
                bhi[j][0] = b.x; blo[j][0] = b.y;
                bhi[j][1] = b.z; blo[j][1] = b.w;
            }
#pragma unroll
            for (int i = 0; i < 2; i++)
#pragma unroll
                for (int j = 0; j < 4; j++) {
                    mma8(acc[i][j], alo[i], bhi[j]);
                    mma8(acc[i][j], ahi[i], blo[j]);
                    mma8(acc[i][j], ahi[i], bhi[j]);
                }
        }
    }

    const float* bias = (stream == 0) ? g.b0 : (stream == 1 ? g.b1 : g.b2);
    int act = (stream == 0) ? g.act0 : (stream == 1 ? g.act1 : g.act2);
    int mm  = (stream == 0) ? g.mm0  : (stream == 1 ? g.mm1  : g.mm2);

#pragma unroll
    for (int i = 0; i < 2; i++) {
#pragma unroll
        for (int p = 0; p < 2; p++) {
            int roff  = wm * 32 + i * 16 + rg + p * 8;
            int rglob = row0 + roff;
            int rloc  = rlocal0 + roff;
            float mk = mm ? g.mask[rloc] : 1.f;
#pragma unroll
            for (int j = 0; j < 4; j++) {
#pragma unroll
                for (int e = 0; e < 2; e++) {
                    int cc = col0 + wn * 32 + j * 8 + q * 2 + e;
                    float v = acc[i][j][p * 2 + e];
                    if (bias)     v += bias[cc];
                    if (g.addsrc) v += g.addsrc[(size_t)rglob * UU + cc];
                    if (g.gamma)
                        v = g.gamma[cc] * (v - g.mean[cc]) * rsqrtf(g.var[cc] + 1e-3f)
                            + g.beta[cc];
                    if (mm == 1) v *= mk;
                    if (act)     v *= 1.f / (1.f + __expf(-v));
                    if (mm == 2) v *= mk;
                    g.C[(size_t)rglob * UU + cc] = v;
                }
            }
        }
    }
}

// ---------------- kv[b] = pk^T @ pv, written as packed planes -----------------
__global__ void __launch_bounds__(256, 2) kv_t(const float* __restrict__ pk,
                                               const float* __restrict__ pv,
                                               uint4* __restrict__ kvp) {
    __shared__ float Ps[32][72];
    __shared__ float Vs[32][72];
    int tid  = threadIdx.x;
    int lane = tid & 31;
    int wid  = tid >> 5;
    int wm   = wid & 1;
    int wn   = wid >> 1;
    int d0 = blockIdx.x * 64, e0 = blockIdx.y * 64, b = blockIdx.z;
    const float* pkb = pk + (size_t)b * NN * UU;
    const float* pvb = pv + (size_t)b * NN * UU;

    float acc[2][2][4];
#pragma unroll
    for (int i = 0; i < 2; i++)
#pragma unroll
        for (int j = 0; j < 2; j++)
#pragma unroll
            for (int e = 0; e < 4; e++) acc[i][j][e] = 0.f;

    int q = lane & 3, rg = lane >> 2;

    for (int n0 = 0; n0 < NN; n0 += 32) {
#pragma unroll
        for (int i = 0; i < 2; i++) {
            int idx = tid + i * 256;
            int kr = idx >> 4, dc = (idx & 15) * 4;
            *(float4*)&Ps[kr][dc] = *(const float4*)(pkb + (size_t)(n0 + kr) * UU + d0 + dc);
            *(float4*)&Vs[kr][dc] = *(const float4*)(pvb + (size_t)(n0 + kr) * UU + e0 + dc);
        }
        __syncthreads();
#pragma unroll
        for (int ks = 0; ks < 4; ks++) {
            int kk = ks * 8;
            uint32_t ahi[2][4], alo[2][4], bhi[2][2], blo[2][2];
#pragma unroll
            for (int i = 0; i < 2; i++) {
                int rr = wm * 32 + i * 16 + rg;
                tsplit(Ps[kk + q    ][rr    ], ahi[i][0], alo[i][0]);
                tsplit(Ps[kk + q    ][rr + 8], ahi[i][1], alo[i][1]);
                tsplit(Ps[kk + q + 4][rr    ], ahi[i][2], alo[i][2]);
                tsplit(Ps[kk + q + 4][rr + 8], ahi[i][3], alo[i][3]);
            }
#pragma unroll
            for (int j = 0; j < 2; j++) {
                int nn = wn * 16 + j * 8 + rg;
                tsplit(Vs[kk + q    ][nn], bhi[j][0], blo[j][0]);
                tsplit(Vs[kk + q + 4][nn], bhi[j][1], blo[j][1]);
            }
#pragma unroll
            for (int i = 0; i < 2; i++)
#pragma unroll
                for (int j = 0; j < 2; j++) {
                    mma8(acc[i][j], alo[i], bhi[j]);
                    mma8(acc[i][j], ahi[i], blo[j]);
                    mma8(acc[i][j], ahi[i], bhi[j]);
                }
        }
        __syncthreads();
    }

    // write packed cells: cell(ksg=d>>3, q=d&3, n=e), half = (d>>2)&1
    uint2* out = (uint2*)(kvp + (size_t)b * 32768);
#pragma unroll
    for (int i = 0; i < 2; i++)
#pragma unroll
        for (int p = 0; p < 2; p++) {
            int dd = d0 + wm * 32 + i * 16 + rg + p * 8;
            int cellb = ((dd >> 3) * 4 + (dd & 3)) * 256;
            int half  = (dd >> 2) & 1;
#pragma unroll
            for (int j = 0; j < 2; j++)
#pragma unroll
                for (int e = 0; e < 2; e++) {
                    int ee = e0 + wn * 16 + j * 8 + q * 2 + e;
                    float v = acc[i][j][p * 2 + e];
                    uint32_t hi, lo;
                    tsplit(v, hi, lo);
                    out[(size_t)(cellb + ee) * 2 + half] = make_uint2(hi, lo);
                }
        }
}

// ---------------- host orchestration -----------------------------------------
extern "C" void kernel_launch(void* const* d_in, const int* in_sizes, int n_in,
                              void* d_out, int out_size) {
    const float* x      = (const float*)d_in[0];
    const float* adj    = (const float*)d_in[1];
    const float* mask   = (const float*)d_in[2];
    const float* W_lin  = (const float*)d_in[3];
    const float* b_lin  = (const float*)d_in[4];
    const float* Wq_mp  = (const float*)d_in[5];
    const float* bq_mp  = (const float*)d_in[6];
    const float* Wk_mp  = (const float*)d_in[7];
    const float* bk_mp  = (const float*)d_in[8];
    const float* Wv_mp  = (const float*)d_in[9];
    const float* bv_mp  = (const float*)d_in[10];
    const float* Wk_att = (const float*)d_in[11];
    const float* Wv_att = (const float*)d_in[12];
    const float* Wq_att = (const float*)d_in[13];
    const float* Wo_att = (const float*)d_in[14];
    const float* gamma  = (const float*)d_in[15];
    const float* beta   = (const float*)d_in[16];
    const float* mean   = (const float*)d_in[17];
    const float* var    = (const float*)d_in[18];
    const float* W_proj = (const float*)d_in[19];
    const float* b_proj = (const float*)d_in[20];
    const float* W_res  = (const float*)d_in[21];
    const float* b_res  = (const float*)d_in[22];

    float *h, *y, *qkv, *t3;
    uint4 *kvp, *wp;
    cudaGetSymbolAddress((void**)&h,   g_h);
    cudaGetSymbolAddress((void**)&y,   g_y);
    cudaGetSymbolAddress((void**)&qkv, g_qkv);
    cudaGetSymbolAddress((void**)&t3,  g_t3);
    cudaGetSymbolAddress((void**)&kvp, g_kvp);
    cudaGetSymbolAddress((void**)&wp,  g_wp);

    // packed weight slices (32768 uint4 each)
    const uint4* P_lin  = wp + 0  * 32768;
    const uint4* P_qmp  = wp + 1  * 32768;   // 3 mats
    const uint4* P_kmp  = wp + 4  * 32768;
    const uint4* P_vmp  = wp + 7  * 32768;
    const uint4* P_katt = wp + 10 * 32768;
    const uint4* P_vatt = wp + 11 * 32768;
    const uint4* P_qatt = wp + 12 * 32768;
    const uint4* P_oatt = wp + 13 * 32768;
    const uint4* P_proj = wp + 14 * 32768;
    const uint4* P_res  = wp + 15 * 32768;

    {
        WTptrs p;
        p.src[0] = W_lin;
        p.src[1] = Wq_mp;  p.src[2] = Wq_mp + UU*UU;  p.src[3] = Wq_mp + 2*UU*UU;
        p.src[4] = Wk_mp;  p.src[5] = Wk_mp + UU*UU;  p.src[6] = Wk_mp + 2*UU*UU;
        p.src[7] = Wv_mp;  p.src[8] = Wv_mp + UU*UU;  p.src[9] = Wv_mp + 2*UU*UU;
        p.src[10] = Wk_att; p.src[11] = Wv_att; p.src[12] = Wq_att; p.src[13] = Wo_att;
        p.src[14] = W_proj; p.src[15] = W_res;
        pack_w<<<dim3(128, 16), 256>>>(p, wp);
    }

    cudaFuncSetAttribute(gemm6, cudaFuncAttributeMaxDynamicSharedMemorySize, SMEM_G);

    dim3 g1(MROWS / 128, UU / 64);       // 512 CTAs
    dim3 g3(3 * MROWS / 128, UU / 64);   // 1536 CTAs

    csr_build<<<MROWS / 8, 256>>>(adj);

    // h = x @ W_lin + b_lin
    { GemmArgs a = {}; a.A = x; a.W0 = P_lin; a.b0 = b_lin; a.C = h;
      gemm6<<<g1, 256, SMEM_G>>>(a); }

    // mp iteration 0: adj@h shared by all three streams
    spmm<<<MROWS / 4, 256>>>(h, t3);
    { GemmArgs a = {}; a.A = t3; a.ashared = 1;
      a.W0 = P_qmp; a.W1 = P_kmp; a.W2 = P_vmp;
      a.b0 = bq_mp; a.b1 = bk_mp; a.b2 = bv_mp;
      a.act0 = a.act1 = a.act2 = 1; a.C = qkv;
      gemm6<<<g3, 256, SMEM_G>>>(a); }

    // mp iterations 1..5
    for (int it = 1; it < 6; it++) {
        int i = it >> 1;
        spmm<<<3 * MROWS / 4, 256>>>(qkv, t3);
        GemmArgs a = {}; a.A = t3;
        a.W0 = P_qmp + (size_t)i * 32768;
        a.W1 = P_kmp + (size_t)i * 32768;
        a.W2 = P_vmp + (size_t)i * 32768;
        a.b0 = bq_mp + i * UU; a.b1 = bk_mp + i * UU; a.b2 = bv_mp + i * UU;
        a.act0 = a.act1 = a.act2 = 1;
        if (it == 5) { a.mm0 = a.mm1 = a.mm2 = 2; a.mask = mask; }
        a.C = qkv;
        gemm6<<<g3, 256, SMEM_G>>>(a);
    }

    // attention projections: pq = q@Wq ; pk = silu((k@Wk)*m) ; pv = (v@Wv)*m
    { GemmArgs a = {}; a.A = qkv;
      a.W0 = P_qatt; a.W1 = P_katt; a.W2 = P_vatt;
      a.act1 = 1; a.mm1 = 1; a.mm2 = 1; a.mask = mask;
      a.C = t3;
      gemm6<<<g3, 256, SMEM_G>>>(a); }

    // kv[b] = pk^T @ pv  (packed output)
    kv_t<<<dim3(UU / 64, UU / 64, BB), 256>>>(t3 + (size_t)MROWS * UU,
                                              t3 + (size_t)2 * MROWS * UU, kvp);

    // attn = pq @ kv[b]
    { GemmArgs a = {}; a.A = t3; a.W0 = kvp; a.perBatchW = 1; a.C = h;
      gemm6<<<g1, 256, SMEM_G>>>(a); }

    // y = BN(attn @ Wo + x)
    { GemmArgs a = {}; a.A = h; a.W0 = P_oatt; a.addsrc = x;
      a.gamma = gamma; a.beta = beta; a.mean = mean; a.var = var; a.C = y;
      gemm6<<<g1, 256, SMEM_G>>>(a); }

    // p = silu(y @ W_proj + b_proj)
    { GemmArgs a = {}; a.A = y; a.W0 = P_proj; a.b0 = b_proj; a.act0 = 1; a.C = t3;
      gemm6<<<g1, 256, SMEM_G>>>(a); }

    // out = (p + x @ W_res + b_res) * mask
    { GemmArgs a = {}; a.A = x; a.W0 = P_res; a.b0 = b_res; a.addsrc = t3;
      a.mm0 = 2; a.mask = mask; a.C = (float*)d_out;
      gemm6<<<g1, 256, SMEM_G>>>(a); }
}